// round 17
// baseline (speedup 1.0000x reference)
#include <cuda_runtime.h>
#include <cuda_bf16.h>

// CenterNet GT heatmap rendering — single fused scatter kernel with a
// software grid barrier: STG zeroing instead of zero-atomics.
//
// hm:      [N, C, H, W] f32 (shape-only)      -> d_in[0]
// bboxes:  [N, nobj, 5] f32 (x1,y1,x2,y2,val) -> d_in[1]
// out:     [N, C, H, W] f32, C == 1
//
// One graph node, grid (32, 16) = 512 blocks x 256 threads. All 512 blocks
// are co-resident in wave 1 (8 blocks/SM by threads, 148 SMs -> 1184 slots),
// so a counter barrier cannot deadlock.
//   1) threads 0..127: STG.128 zero of this block's 512-px segment of its
//      batch plane (overwrites poison/any prior replay state).
//   2) __syncthreads; tid0: __threadfence (release the zeros to gpu scope,
//      cumulativity covers the other threads' stores ordered by bar.sync),
//      atomicAdd on the per-batch counter, spin until all 32 blocks of this
//      batch arrived. Counters are monotonic: target = old - old%32 + 32,
//      correct across graph replays with no reset.
//   3) render: warp 0 lanes 0..3 computed the 4 objects' params during the
//      barrier window; 2 warps per object, rows strided by 2, warp spans a
//      full patch row (width = 2r+1 <= 21 < 32); hoisted x-factor and
//      incremental row exponential; values via atomicMax(s32) — valid since
//      all values on the plane are 0 or gaussians >= 0 (commutative,
//      idempotent max-join).

#define HN 16
#define HC 1
#define HH 128
#define HW 128
#define NOBJ 128
#define OBJ_PER_BLK 4
#define BLK_X (NOBJ / OBJ_PER_BLK)     // 32 blocks per batch
#define NTHREADS 256                   // 8 warps: 2 per object
#define MIN_OVERLAP 0.7f

__device__ int g_ctr[HN];              // zero-init at load; monotonic forever

__device__ __forceinline__ float gaussian_radius_f(float w, float h) {
    // mirrors the reference fp32 math op-for-op
    const float mo = MIN_OVERLAP;
    float b1 = h + w;
    float c1 = w * h * ((1.0f - mo) / (1.0f + mo));
    float sq1 = sqrtf(b1 * b1 - 4.0f * 1.0f * c1);
    float r1 = (b1 + sq1) * 0.5f;

    float b2 = 2.0f * (h + w);
    float c2 = (1.0f - mo) * w * h;
    float sq2 = sqrtf(b2 * b2 - 4.0f * 4.0f * c2);
    float r2 = (b2 + sq2) * 0.5f;

    float a3 = 4.0f * mo;
    float b3 = -2.0f * mo * (h + w);
    float c3 = (mo - 1.0f) * w * h;
    float sq3 = sqrtf(b3 * b3 - 4.0f * a3 * c3);
    float r3 = (b3 + sq3) * 0.5f;

    return fminf(fminf(r1, r2), r3);
}

__global__ void __launch_bounds__(NTHREADS)
cn_fused_kernel(const float* __restrict__ bboxes,
                float* __restrict__ out) {
    __shared__ float4 s_par[OBJ_PER_BLK];   // {cx, cy, r, c}, r<0 = skip

    const int tid   = threadIdx.x;
    const int wid   = tid >> 5;
    const int lane  = tid & 31;
    const int bx    = blockIdx.x;           // 0..31
    const int batch = blockIdx.y;           // 0..15

    float* plane = out + batch * (HH * HW);

    // ---- issue bbox loads first (latency hides under zero+barrier) ----
    float x1, y1, x2, y2, valf;
    if (tid < OBJ_PER_BLK) {
        const float* p = bboxes + (batch * NOBJ + bx * OBJ_PER_BLK + tid) * 5;
        x1 = p[0] * (float)HW;
        y1 = p[1] * (float)HH;
        x2 = p[2] * (float)HW;
        y2 = p[3] * (float)HH;
        valf = p[4];
    }

    // ---- 1) zero this block's 512-px segment: STG.128, threads 0..127 ----
    if (tid < 128)
        ((float4*)plane)[bx * 128 + tid] = make_float4(0.f, 0.f, 0.f, 0.f);

    __syncthreads();                        // block's zeros done

    // ---- 2a) arrive at the per-batch barrier (release the zeros) ----
    int target = 0;
    if (tid == 0) {
        __threadfence();                    // zeros -> gpu scope (cumulative)
        int old = atomicAdd(&g_ctr[batch], 1);
        target = old - (old & (BLK_X - 1)) + BLK_X;
    }

    // ---- params for the 4 objects while other blocks arrive ----
    if (tid < OBJ_PER_BLK) {
        float bw = x2 - x1;
        float bh = y2 - y1;
        float4 q = make_float4(0.f, 0.f, -1.f, 0.f);    // default: skip
        if (valf == 1.0f && bw > 0.0f && bh > 0.0f) {
            float r = gaussian_radius_f(bw, bh);
            if (!(r == r)) r = 0.0f;        // jnp.nan_to_num
            r = fmaxf(r, 0.0f);

            int ri  = (int)r;               // trunc toward zero, r >= 0
            int cxi = (int)((x1 + x2) * 0.5f);
            int cyi = (int)((y1 + y2) * 0.5f);

            float sigma = (float)(2 * ri + 1) / 6.0f;
            float c = -1.0f / (2.0f * sigma * sigma);
            q = make_float4((float)cxi, (float)cyi, (float)ri, c);
        }
        s_par[tid] = q;
    }

    // ---- 2b) wait for all 32 blocks of this batch ----
    if (tid == 0) {
        while (*(volatile int*)&g_ctr[batch] < target) { }
        __threadfence();                    // acquire side
    }
    __syncthreads();

    // ---- 3) render: 2 warps per object, rows strided by 2 ----
    const float4 q = s_par[wid >> 1];       // broadcast LDS.128
    if (q.z < 0.0f) return;                 // warp-uniform skip

    const int sub = wid & 1;
    const int ri  = (int)q.z;
    const int cxi = (int)q.x;
    const int cyi = (int)q.y;
    const float c = q.w;

    // lane covers dx = lane - ri, valid while lane <= 2*ri (width <= 21 < 32)
    int dx = lane - ri;
    int xx = cxi + dx;
    bool xok = (lane <= 2 * ri) && ((unsigned)xx < HW);
    float ex = __expf((float)(dx * dx) * c);   // hoisted x-factor

    // pre-clamped row range, parity-aligned to this warp
    int dy_lo = max(-ri, -cyi);
    int dy_hi = min(ri, (HH - 1) - cyi);
    int dy0 = dy_lo + ((dy_lo + ri + sub) & 1);
    if (dy0 > dy_hi) return;

    // incremental row exponential: ey(dy+2) = ey(dy) * f,  f *= e^{8c}
    float ey = __expf((float)(dy0 * dy0) * c);
    float f  = __expf((float)(4 * dy0 + 4) * c);
    float u  = __expf(8.0f * c);

    int* ptr = (int*)plane + (cyi + dy0) * HW + xx;
    int rows = ((dy_hi - dy0) >> 1) + 1;

    for (int n = 0; n < rows; n++) {
        float g = ex * ey;
        if (xok)
            atomicMax(ptr, __float_as_int(g));
        ey *= f;
        f  *= u;
        ptr += 2 * HW;
    }
}

extern "C" void kernel_launch(void* const* d_in, const int* in_sizes, int n_in,
                              void* d_out, int out_size) {
    const float* bboxes = (const float*)d_in[1];
    float* out = (float*)d_out;

    dim3 grid(BLK_X, HN);   // (32, 16) = 512 blocks
    cn_fused_kernel<<<grid, NTHREADS>>>(bboxes, out);
}